// round 13
// baseline (speedup 1.0000x reference)
#include <cuda_runtime.h>
#include <cuda_bf16.h>
#include <cstdint>

// Problem constants
#define B_   2
#define S_   2048
#define H_   2048
#define NH_  16
#define NKV_ 4
#define HD_  128
#define SCALE_ 0.08838834764831845f   // 1/sqrt(128)

// Scratch (module-load static device arrays; no runtime allocation)
__device__ float g_q[B_*S_*NH_*HD_];
__device__ float g_k[B_*S_*NKV_*HD_];
__device__ float g_v[B_*S_*NKV_*HD_];
__device__ float g_attn[B_*S_*NH_*HD_];

#define BUF_EXT  0
#define BUF_Q    1
#define BUF_K    2
#define BUF_V    3
#define BUF_ATTN 4

__device__ __forceinline__ float* sel_buf(int sel, float* ext) {
    switch (sel) {
        case BUF_Q:    return g_q;
        case BUF_K:    return g_k;
        case BUF_V:    return g_v;
        case BUF_ATTN: return g_attn;
        default:       return ext;
    }
}

__device__ __forceinline__ uint32_t f2tf32(float x) {
    uint32_t r;
    asm("cvt.rna.tf32.f32 %0, %1;" : "=r"(r) : "f"(x));
    return r;
}

__device__ __forceinline__ void mma_tf32(float* d, const uint32_t* a, const uint32_t* b) {
    asm volatile(
        "mma.sync.aligned.m16n8k8.row.col.f32.tf32.tf32.f32 "
        "{%0,%1,%2,%3}, {%4,%5,%6,%7}, {%8,%9}, {%0,%1,%2,%3};"
        : "+f"(d[0]), "+f"(d[1]), "+f"(d[2]), "+f"(d[3])
        : "r"(a[0]), "r"(a[1]), "r"(a[2]), "r"(a[3]), "r"(b[0]), "r"(b[1]));
}

__device__ __forceinline__ void mma_bf16(float* d, const uint32_t* a, const uint32_t* b) {
    asm volatile(
        "mma.sync.aligned.m16n8k16.row.col.f32.bf16.bf16.f32 "
        "{%0,%1,%2,%3}, {%4,%5,%6,%7}, {%8,%9}, {%0,%1,%2,%3};"
        : "+f"(d[0]), "+f"(d[1]), "+f"(d[2]), "+f"(d[3])
        : "r"(a[0]), "r"(a[1]), "r"(a[2]), "r"(a[3]), "r"(b[0]), "r"(b[1]));
}

__device__ __forceinline__ uint32_t bf16_pack2(float x0, float x1) {
    __nv_bfloat162 p;
    p.x = __float2bfloat16_rn(x0);
    p.y = __float2bfloat16_rn(x1);
    return *reinterpret_cast<uint32_t*>(&p);
}

__device__ __forceinline__ void bf16_split2(float x0, float x1, uint32_t& hi, uint32_t& lo) {
    __nv_bfloat16 h0 = __float2bfloat16_rn(x0);
    __nv_bfloat16 h1 = __float2bfloat16_rn(x1);
    __nv_bfloat162 hp; hp.x = h0; hp.y = h1;
    hi = *reinterpret_cast<uint32_t*>(&hp);
    __nv_bfloat162 lp;
    lp.x = __float2bfloat16_rn(x0 - __bfloat162float(h0));
    lp.y = __float2bfloat16_rn(x1 - __bfloat162float(h1));
    lo = *reinterpret_cast<uint32_t*>(&lp);
}

__device__ __forceinline__ void cp_async16(uint32_t saddr, const void* gptr) {
    asm volatile("cp.async.ca.shared.global [%0], [%1], 16;" :: "r"(saddr), "l"(gptr));
}
__device__ __forceinline__ void cp_async_commit() {
    asm volatile("cp.async.commit_group;");
}

// ---------------------------------------------------------------------------
// TF32 tensor-core GEMM, cp.async double-buffered raw staging.
// Same fragment math / mma / epilogue as the R4-R11 kernel; only the tile
// ingress changed: global -> raw smem ring (async) -> convert -> frag smem.
// Dynamic smem: rawA 2x16KB + rawB 2x16KB + Asf 16KB + Bsf 16KB = 96KB.
// ---------------------------------------------------------------------------
#define TBM 128
#define TBN 128
#define TBK 32
#define GEMM_SMEM 98304

__device__ __forceinline__ void gemm_issue_tile(
    const float* __restrict__ A, const float* __restrict__ W,
    uint32_t rawA_b, uint32_t rawB_b,
    int m0, int n0, int k0, int K, int N, int tid, int buf)
{
#pragma unroll
    for (int i = 0; i < 4; i++) {
        int f   = tid + i * 256;
        int row = f >> 3;
        int c4  = (f & 7) << 2;
        cp_async16(rawA_b + (uint32_t)((buf * 4096 + row * 32 + c4) * 4),
                   &A[(size_t)(m0 + row) * K + k0 + c4]);
    }
#pragma unroll
    for (int i = 0; i < 4; i++) {
        int f  = tid + i * 256;
        int r  = f >> 5;
        int c4 = (f & 31) << 2;
        cp_async16(rawB_b + (uint32_t)((buf * 4096 + r * 128 + c4) * 4),
                   &W[(size_t)(k0 + r) * N + n0 + c4]);
    }
    cp_async_commit();
}

__device__ __forceinline__ void gemm_convert(
    const float* __restrict__ rawA, const float* __restrict__ rawB,
    uint32_t* __restrict__ Asf, uint32_t* __restrict__ Bsf,
    int tid, int buf)
{
#pragma unroll
    for (int i = 0; i < 4; i++) {
        int f   = tid + i * 256;
        int row = f >> 3;
        int c4  = (f & 7) << 2;
        const float4 a = *(const float4*)&rawA[buf * 4096 + row * 32 + c4];
        const float av[4] = {a.x, a.y, a.z, a.w};
        int mt = row >> 4;
        int g  = row & 15;
        int gl = (g & 7) << 2;
        int ib = (g >= 8) ? 1 : 0;
#pragma unroll
        for (int e = 0; e < 4; e++) {
            int col = c4 + e;
            int ks  = col >> 3;
            int c   = col & 7;
            int idx = ib | ((c >= 4) ? 2 : 0);
            int ln  = (gl | (c & 3)) ^ ks;
            Asf[(((mt << 2) + ks) << 7) + (ln << 2) + idx] = f2tf32(av[e]);
        }
    }
#pragma unroll
    for (int i = 0; i < 4; i++) {
        int f  = tid + i * 256;
        int r  = f >> 5;
        int c4 = (f & 31) << 2;
        const float4 b4 = *(const float4*)&rawB[buf * 4096 + r * 128 + c4];
        const float bv[4] = {b4.x, b4.y, b4.z, b4.w};
        int ks = r >> 3;
        int kc = r & 7;
        int ib = (kc >= 4) ? 1 : 0;
        int kl = kc & 3;
#pragma unroll
        for (int e = 0; e < 4; e++) {
            int n  = c4 + e;
            int nt = n >> 3;
            int gn = n & 7;
            int ln = ((gn << 2) | kl) ^ (nt & 15);
            Bsf[(((nt << 2) + ks) << 6) + (ln << 1) + ib] = f2tf32(bv[e]);
        }
    }
}

__global__ __launch_bounds__(256, 2)
void gemm_tf32_p(int a_sel, float* a_ext,
                 const float* __restrict__ W,
                 const float* __restrict__ bias,
                 int c_sel, float* c_ext,
                 int M, int N, int K)
{
    const float* __restrict__ A = sel_buf(a_sel, a_ext);
    float* __restrict__ C = sel_buf(c_sel, c_ext);

    extern __shared__ float smf[];
    float* rawA = smf;                             // [2][4096]
    float* rawB = smf + 8192;                      // [2][4096]
    uint32_t* Asf = (uint32_t*)(smf + 16384);      // 4096 words
    uint32_t* Bsf = Asf + 4096;                    // 4096 words
    const uint32_t rawA_b = (uint32_t)__cvta_generic_to_shared(rawA);
    const uint32_t rawB_b = (uint32_t)__cvta_generic_to_shared(rawB);

    const int tid  = threadIdx.x;
    const int lane = tid & 31;
    const int wid  = tid >> 5;
    const int wm   = wid >> 2;
    const int wn   = wid & 3;
    const int m0   = blockIdx.y * TBM;
    const int n0   = blockIdx.x * TBN;

    float acc[4][4][4];
#pragma unroll
    for (int i = 0; i < 4; i++)
#pragma unroll
        for (int j = 0; j < 4; j++)
#pragma unroll
            for (int r = 0; r < 4; r++) acc[i][j][r] = 0.f;

    gemm_issue_tile(A, W, rawA_b, rawB_b, m0, n0, 0, K, N, tid, 0);

    const int nk = K / TBK;
    for (int kt = 0; kt < nk; kt++) {
        if (kt + 1 < nk) {
            gemm_issue_tile(A, W, rawA_b, rawB_b, m0, n0, (kt + 1) * TBK, K, N, tid, (kt + 1) & 1);
            asm volatile("cp.async.wait_group 1;");
        } else {
            asm volatile("cp.async.wait_group 0;");
        }
        __syncthreads();   // raw tile kt visible; also guards frag reuse from prev iter

        gemm_convert(rawA, rawB, Asf, Bsf, tid, kt & 1);
        __syncthreads();   // frags ready

#pragma unroll
        for (int ks = 0; ks < 4; ks++) {
            uint32_t af[4][4];
            uint32_t bf[4][2];
#pragma unroll
            for (int am = 0; am < 4; am++) {
                int mt = (wm << 2) + am;
                *(uint4*)af[am] = *(const uint4*)&Asf[(((mt << 2) + ks) << 7) + ((lane ^ ks) << 2)];
            }
#pragma unroll
            for (int bn = 0; bn < 4; bn++) {
                int nt = (wn << 2) + bn;
                *(uint2*)bf[bn] = *(const uint2*)&Bsf[(((nt << 2) + ks) << 6) + ((lane ^ (nt & 15)) << 1)];
            }
#pragma unroll
            for (int am = 0; am < 4; am++)
#pragma unroll
                for (int bn = 0; bn < 4; bn++)
                    mma_tf32(acc[am][bn], af[am], bf[bn]);
        }
        // no trailing sync: next iteration's top syncthreads (after wait_group)
        // guarantees all warps finished this mma before frags are overwritten.
    }

    const int g = lane >> 2;
    const int t = lane & 3;
#pragma unroll
    for (int bn = 0; bn < 4; bn++) {
        int col = n0 + wn * 32 + bn * 8 + t * 2;
        float2 bb = *(const float2*)&bias[col];
#pragma unroll
        for (int am = 0; am < 4; am++) {
            int row = m0 + wm * 64 + am * 16 + g;
            float2 o0, o1;
            o0.x = acc[am][bn][0] + bb.x;  o0.y = acc[am][bn][1] + bb.y;
            o1.x = acc[am][bn][2] + bb.x;  o1.y = acc[am][bn][3] + bb.y;
            *(float2*)&C[(size_t)row * N + col]       = o0;
            *(float2*)&C[(size_t)(row + 8) * N + col] = o1;
        }
    }
}

// ---------------------------------------------------------------------------
// RoPE in place on g_q / g_k.
// ---------------------------------------------------------------------------
__global__ void rope_kernel(const float* __restrict__ cosb, const float* __restrict__ sinb)
{
    int idx = blockIdx.x * 256 + threadIdx.x;
    const int d  = idx & 63;  idx >>= 6;
    const int hh = idx % (NH_ + NKV_);
    const int bs = idx / (NH_ + NKV_);

    const float c1 = cosb[(size_t)bs * HD_ + d];
    const float s1 = sinb[(size_t)bs * HD_ + d];
    const float c2 = cosb[(size_t)bs * HD_ + d + 64];
    const float s2 = sinb[(size_t)bs * HD_ + d + 64];

    float* base;
    if (hh < NH_) base = g_q + ((size_t)bs * NH_ + hh) * HD_;
    else          base = g_k + ((size_t)bs * NKV_ + (hh - NH_)) * HD_;

    const float x1 = base[d];
    const float x2 = base[d + 64];
    base[d]      = x1 * c1 - x2 * s1;
    base[d + 64] = x2 * c2 + x1 * s2;
}

// ---------------------------------------------------------------------------
// bf16 tensor-core flash attention, fully error-compensated (R11, passing).
// ---------------------------------------------------------------------------
#define AQ2 128
#define AKT 32
#define QF_WORDS (8*8*32*4)
#define KF_WORDS (4*8*32*2)
#define VF_WORDS (16*2*32*2)

__device__ __forceinline__ void attn_load_regs(
    const float* __restrict__ Kg, const float* __restrict__ Vg,
    int b, int kvh, int j0, int tid,
    float4* kreg, float4* vreg0, float4* vreg1)
{
#pragma unroll
    for (int i = 0; i < 4; i++) {
        int f   = tid + i * 256;
        int key = f >> 5;
        int c4  = (f & 31) << 2;
        kreg[i] = *(const float4*)&Kg[(((size_t)b * S_ + j0 + key) * NKV_ + kvh) * HD_ + c4];
    }
#pragma unroll
    for (int i = 0; i < 2; i++) {
        int f   = tid + i * 256;
        int kp  = f >> 5;
        int c4  = (f & 31) << 2;
        vreg0[i] = *(const float4*)&Vg[(((size_t)b * S_ + j0 + 2*kp)     * NKV_ + kvh) * HD_ + c4];
        vreg1[i] = *(const float4*)&Vg[(((size_t)b * S_ + j0 + 2*kp + 1) * NKV_ + kvh) * HD_ + c4];
    }
}

__device__ __forceinline__ void attn_store_frags(
    uint32_t* __restrict__ KfHi, uint32_t* __restrict__ KfLo,
    uint32_t* __restrict__ VfHi, uint32_t* __restrict__ VfLo, int tid,
    const float4* kreg, const float4* vreg0, const float4* vreg1)
{
#pragma unroll
    for (int i = 0; i < 4; i++) {
        int f   = tid + i * 256;
        int key = f >> 5;
        int c4  = (f & 31) << 2;
        int nt  = key >> 3;
        int g   = key & 7;
        const float kv[4] = {kreg[i].x, kreg[i].y, kreg[i].z, kreg[i].w};
        int ks  = c4 >> 4;
        int base_uu = (c4 & 15) >> 1;
#pragma unroll
        for (int p = 0; p < 2; p++) {
            int c   = (c4 & 15) + 2 * p;
            int reg = (c >= 8) ? 1 : 0;
            int uu  = base_uu + p;
            int ln  = (g * 4 + (uu & 3)) ^ ks;
            int off = ((((nt << 3) + ks) << 5) + ln) * 2 + reg;
            uint32_t hi, lo;
            bf16_split2(kv[2*p], kv[2*p+1], hi, lo);
            KfHi[off] = hi;
            KfLo[off] = lo;
        }
    }
#pragma unroll
    for (int i = 0; i < 2; i++) {
        int f   = tid + i * 256;
        int kp  = f >> 5;
        int c4  = (f & 31) << 2;
        int kt  = kp >> 3;
        int uu  = kp & 3;
        int reg = ((kp & 7) >= 4) ? 1 : 0;
        const float v0[4] = {vreg0[i].x, vreg0[i].y, vreg0[i].z, vreg0[i].w};
        const float v1[4] = {vreg1[i].x, vreg1[i].y, vreg1[i].z, vreg1[i].w};
#pragma unroll
        for (int e = 0; e < 4; e++) {
            int hd  = c4 + e;
            int nt2 = hd >> 3;
            int g   = hd & 7;
            int ln  = (g * 4 + uu) ^ (nt2 & 7);
            int off = ((((nt2 << 1) + kt) << 5) + ln) * 2 + reg;
            uint32_t hi, lo;
            bf16_split2(v0[e], v1[e], hi, lo);
            VfHi[off] = hi;
            VfLo[off] = lo;
        }
    }
}

__global__ __launch_bounds__(256, 1)
void attn_mma_v2()
{
    extern __shared__ uint32_t smu[];
    uint32_t* QfHi = smu;
    uint32_t* QfLo = QfHi + QF_WORDS;
    uint32_t* KfHi = QfLo + QF_WORDS;
    uint32_t* KfLo = KfHi + KF_WORDS;
    uint32_t* VfHi = KfLo + KF_WORDS;
    uint32_t* VfLo = VfHi + VF_WORDS;

    const int tid  = threadIdx.x;
    const int lane = tid & 31;
    const int wid  = tid >> 5;
    const int u    = lane & 3;
    const int qd   = lane >> 2;
    const int bh   = blockIdx.y;
    const int b    = bh >> 4;
    const int h    = bh & 15;
    const int kvh  = h >> 2;
    const int q0   = blockIdx.x * AQ2;

    const float* __restrict__ Qg = g_q;
    const float* __restrict__ Kg = g_k;
    const float* __restrict__ Vg = g_v;

    {
        const int row  = tid >> 1;
        const int c0   = (tid & 1) * 64;
        const float* qrow = &Qg[(((size_t)b * S_ + q0 + row) * NH_ + h) * HD_];
        const int mt   = row >> 4;
        const int r15  = row & 15;
        const int g    = r15 & 7;
        const int rbit = (r15 >= 8) ? 1 : 0;
#pragma unroll
        for (int cc = 0; cc < 64; cc += 4) {
            float4 qv = *(const float4*)&qrow[c0 + cc];
            const float xv[4] = {qv.x * SCALE_, qv.y * SCALE_, qv.z * SCALE_, qv.w * SCALE_};
#pragma unroll
            for (int p = 0; p < 2; p++) {
                int col = c0 + cc + 2 * p;
                int ks  = col >> 4;
                int c   = col & 15;
                int reg = rbit + ((c >= 8) ? 2 : 0);
                int uu  = (c & 7) >> 1;
                int off = (((mt << 3) + ks) << 7) + ((g * 4 + uu) << 2) + reg;
                uint32_t hi, lo;
                bf16_split2(xv[2*p], xv[2*p+1], hi, lo);
                QfHi[off] = hi;
                QfLo[off] = lo;
            }
        }
    }

    float4 kreg[4], vreg0[2], vreg1[2];
    attn_load_regs(Kg, Vg, b, kvh, 0, tid, kreg, vreg0, vreg1);
    attn_store_frags(KfHi, KfLo, VfHi, VfLo, tid, kreg, vreg0, vreg1);

    float Oacc[16][4];
#pragma unroll
    for (int i = 0; i < 16; i++)
#pragma unroll
        for (int r = 0; r < 4; r++) Oacc[i][r] = 0.f;
    float m0 = -1.0e30f, m1 = -1.0e30f, l0 = 0.f, l1 = 0.f;

    __syncthreads();

    const int NTILES = S_ / AKT;

    for (int jt = 0; jt < NTILES; jt++) {
        if (jt + 1 < NTILES)
            attn_load_regs(Kg, Vg, b, kvh, (jt + 1) * AKT, tid, kreg, vreg0, vreg1);

        float Sacc[4][4];
#pragma unroll
        for (int i = 0; i < 4; i++)
#pragma unroll
            for (int r = 0; r < 4; r++) Sacc[i][r] = 0.f;

#pragma unroll
        for (int ks = 0; ks < 8; ks++) {
            uint32_t ahi[4], alo[4];
            int aoff = (((wid << 3) + ks) << 7) + (lane << 2);
            *(uint4*)ahi = *(const uint4*)&QfHi[aoff];
            *(uint4*)alo = *(const uint4*)&QfLo[aoff];
#pragma unroll
            for (int nt = 0; nt < 4; nt++) {
                int koff = ((((nt << 3) + ks) << 5) + (lane ^ ks)) * 2;
                uint32_t bh_[2], bl_[2];
                *(uint2*)bh_ = *(const uint2*)&KfHi[koff];
                *(uint2*)bl_ = *(const uint2*)&KfLo[koff];
                mma_bf16(Sacc[nt], ahi, bh_);
                mma_bf16(Sacc[nt], ahi, bl_);
                mma_bf16(Sacc[nt], alo, bh_);
            }
        }

        float mx0 = -1.0e30f, mx1 = -1.0e30f;
#pragma unroll
        for (int nt = 0; nt < 4; nt++) {
            mx0 = fmaxf(mx0, fmaxf(Sacc[nt][0], Sacc[nt][1]));
            mx1 = fmaxf(mx1, fmaxf(Sacc[nt][2], Sacc[nt][3]));
        }
        mx0 = fmaxf(mx0, __shfl_xor_sync(0xffffffffu, mx0, 1));
        mx0 = fmaxf(mx0, __shfl_xor_sync(0xffffffffu, mx0, 2));
        mx1 = fmaxf(mx1, __shfl_xor_sync(0xffffffffu, mx1, 1));
        mx1 = fmaxf(mx1, __shfl_xor_sync(0xffffffffu, mx1, 2));

        float mn0 = fmaxf(m0, mx0);
        float mn1 = fmaxf(m1, mx1);
        float fs0 = __expf(m0 - mn0);
        float fs1 = __expf(m1 - mn1);
        m0 = mn0;  m1 = mn1;

        float P[4][4];
        float s0 = 0.f, s1 = 0.f;
#pragma unroll
        for (int nt = 0; nt < 4; nt++) {
            P[nt][0] = __expf(Sacc[nt][0] - m0);
            P[nt][1] = __expf(Sacc[nt][1] - m0);
            P[nt][2] = __expf(Sacc[nt][2] - m1);
            P[nt][3] = __expf(Sacc[nt][3] - m1);
            s0 += P[nt][0] + P[nt][1];
            s1 += P[nt][2] + P[nt][3];
        }
        s0 += __shfl_xor_sync(0xffffffffu, s0, 1);
        s0 += __shfl_xor_sync(0xffffffffu, s0, 2);
        s1 += __shfl_xor_sync(0xffffffffu, s1, 1);
        s1 += __shfl_xor_sync(0xffffffffu, s1, 2);
        l0 = l0 * fs0 + s0;
        l1 = l1 * fs1 + s1;

#pragma unroll
        for (int i = 0; i < 16; i++) {
            Oacc[i][0] *= fs0;  Oacc[i][1] *= fs0;
            Oacc[i][2] *= fs1;  Oacc[i][3] *= fs1;
        }

#pragma unroll
        for (int kt = 0; kt < 2; kt++) {
            uint32_t ah[4], al[4];
            bf16_split2(P[2*kt][0],   P[2*kt][1],   ah[0], al[0]);
            bf16_split2(P[2*kt][2],   P[2*kt][3],   ah[1], al[1]);
            bf16_split2(P[2*kt+1][0], P[2*kt+1][1], ah[2], al[2]);
            bf16_split2(P[2*kt+1][2], P[2*kt+1][3], ah[3], al[3]);
#pragma unroll
            for (int nt2 = 0; nt2 < 16; nt2++) {
                int voff = ((((nt2 << 1) + kt) << 5) + (lane ^ (nt2 & 7))) * 2;
                uint32_t bvh[2], bvl[2];
                *(uint2*)bvh = *(const uint2*)&VfHi[voff];
                *(uint2*)bvl = *(const uint2*)&VfLo[voff];
                mma_bf16(Oacc[nt2], ah, bvh);
                mma_bf16(Oacc[nt2], ah, bvl);
                mma_bf16(Oacc[nt2], al, bvh);
            }
        }

        __syncthreads();
        if (jt + 1 < NTILES)
            attn_store_frags(KfHi, KfLo, VfHi, VfLo, tid, kreg, vreg0, vreg1);
        __syncthreads();
    }

    const float inv0 = 1.0f / l0;
    const float inv1 = 1.0f / l1;
    const int row0 = q0 + wid * 16 + qd;
    const size_t rbase0 = ((size_t)b * S_ + row0)     * (NH_ * HD_) + h * HD_ + 2 * u;
    const size_t rbase1 = ((size_t)b * S_ + row0 + 8) * (NH_ * HD_) + h * HD_ + 2 * u;
    float* __restrict__ Out = g_attn;
#pragma unroll
    for (int nt2 = 0; nt2 < 16; nt2++) {
        float2 o0, o1;
        o0.x = Oacc[nt2][0] * inv0;  o0.y = Oacc[nt2][1] * inv0;
        o1.x = Oacc[nt2][2] * inv1;  o1.y = Oacc[nt2][3] * inv1;
        *(float2*)&Out[rbase0 + nt2 * 8] = o0;
        *(float2*)&Out[rbase1 + nt2 * 8] = o1;
    }
}

// ---------------------------------------------------------------------------
extern "C" void kernel_launch(void* const* d_in, const int* in_sizes, int n_in,
                              void* d_out, int out_size)
{
    float* hidden = (float*)d_in[0];
    const float* cosb   = (const float*)d_in[1];
    const float* sinb   = (const float*)d_in[2];
    const float* Wq     = (const float*)d_in[3];
    const float* bq     = (const float*)d_in[4];
    const float* Wk     = (const float*)d_in[5];
    const float* bk     = (const float*)d_in[6];
    const float* Wv     = (const float*)d_in[7];
    const float* bv     = (const float*)d_in[8];
    const float* Wo     = (const float*)d_in[9];
    const float* bo     = (const float*)d_in[10];
    float* out = (float*)d_out;

    const int M = B_ * S_;

    cudaFuncSetAttribute(gemm_tf32_p, cudaFuncAttributeMaxDynamicSharedMemorySize, GEMM_SMEM);

    gemm_tf32_p<<<dim3((NH_*HD_) / TBN, M / TBM), 256, GEMM_SMEM>>>(BUF_EXT, hidden, Wq, bq, BUF_Q, nullptr, M, NH_*HD_, H_);
    gemm_tf32_p<<<dim3((NKV_*HD_) / TBN, M / TBM), 256, GEMM_SMEM>>>(BUF_EXT, hidden, Wk, bk, BUF_K, nullptr, M, NKV_*HD_, H_);
    gemm_tf32_p<<<dim3((NKV_*HD_) / TBN, M / TBM), 256, GEMM_SMEM>>>(BUF_EXT, hidden, Wv, bv, BUF_V, nullptr, M, NKV_*HD_, H_);

    {
        int total = B_ * S_ * (NH_ + NKV_) * 64;
        rope_kernel<<<total / 256, 256>>>(cosb, sinb);
    }

    {
        int smem = (2 * QF_WORDS + 2 * KF_WORDS + 2 * VF_WORDS) * (int)sizeof(uint32_t);  // 96KB
        cudaFuncSetAttribute(attn_mma_v2, cudaFuncAttributeMaxDynamicSharedMemorySize, smem);
        attn_mma_v2<<<dim3(S_ / AQ2, B_ * NH_), 256, smem>>>();
    }

    gemm_tf32_p<<<dim3(H_ / TBN, M / TBM), 256, GEMM_SMEM>>>(BUF_ATTN, nullptr, Wo, bo, BUF_EXT, out, M, H_, NH_*HD_);
}

// round 14
// speedup vs baseline: 1.0012x; 1.0012x over previous
#include <cuda_runtime.h>
#include <cuda_bf16.h>
#include <cstdint>

// Problem constants
#define B_   2
#define S_   2048
#define H_   2048
#define NH_  16
#define NKV_ 4
#define HD_  128
#define SCALE_ 0.08838834764831845f   // 1/sqrt(128)

// Scratch (module-load static device arrays; no runtime allocation)
__device__ float g_q[B_*S_*NH_*HD_];
__device__ float g_k[B_*S_*NKV_*HD_];
__device__ float g_v[B_*S_*NKV_*HD_];
__device__ float g_attn[B_*S_*NH_*HD_];

#define BUF_EXT  0
#define BUF_Q    1
#define BUF_K    2
#define BUF_V    3
#define BUF_ATTN 4

__device__ __forceinline__ float* sel_buf(int sel, float* ext) {
    switch (sel) {
        case BUF_Q:    return g_q;
        case BUF_K:    return g_k;
        case BUF_V:    return g_v;
        case BUF_ATTN: return g_attn;
        default:       return ext;
    }
}

__device__ __forceinline__ uint32_t f2tf32(float x) {
    uint32_t r;
    asm("cvt.rna.tf32.f32 %0, %1;" : "=r"(r) : "f"(x));
    return r;
}

__device__ __forceinline__ void mma_tf32(float* d, const uint32_t* a, const uint32_t* b) {
    asm volatile(
        "mma.sync.aligned.m16n8k8.row.col.f32.tf32.tf32.f32 "
        "{%0,%1,%2,%3}, {%4,%5,%6,%7}, {%8,%9}, {%0,%1,%2,%3};"
        : "+f"(d[0]), "+f"(d[1]), "+f"(d[2]), "+f"(d[3])
        : "r"(a[0]), "r"(a[1]), "r"(a[2]), "r"(a[3]), "r"(b[0]), "r"(b[1]));
}

__device__ __forceinline__ void mma_bf16(float* d, const uint32_t* a, const uint32_t* b) {
    asm volatile(
        "mma.sync.aligned.m16n8k16.row.col.f32.bf16.bf16.f32 "
        "{%0,%1,%2,%3}, {%4,%5,%6,%7}, {%8,%9}, {%0,%1,%2,%3};"
        : "+f"(d[0]), "+f"(d[1]), "+f"(d[2]), "+f"(d[3])
        : "r"(a[0]), "r"(a[1]), "r"(a[2]), "r"(a[3]), "r"(b[0]), "r"(b[1]));
}

__device__ __forceinline__ uint32_t bf16_pack2(float x0, float x1) {
    __nv_bfloat162 p;
    p.x = __float2bfloat16_rn(x0);
    p.y = __float2bfloat16_rn(x1);
    return *reinterpret_cast<uint32_t*>(&p);
}

__device__ __forceinline__ void bf16_split2(float x0, float x1, uint32_t& hi, uint32_t& lo) {
    __nv_bfloat16 h0 = __float2bfloat16_rn(x0);
    __nv_bfloat16 h1 = __float2bfloat16_rn(x1);
    __nv_bfloat162 hp; hp.x = h0; hp.y = h1;
    hi = *reinterpret_cast<uint32_t*>(&hp);
    __nv_bfloat162 lp;
    lp.x = __float2bfloat16_rn(x0 - __bfloat162float(h0));
    lp.y = __float2bfloat16_rn(x1 - __bfloat162float(h1));
    lo = *reinterpret_cast<uint32_t*>(&lp);
}

// ---------------------------------------------------------------------------
// TF32 tensor-core GEMM, 256x128 block tile, register-prefetch pipeline.
// 256 threads = 8 warps (4m x 2n), warp tile 64x64 (4 m16-tiles x 8 n8-tiles).
// Per K-tile/thread: 128 mma vs 48 STS + 48 cvt (was 64:64). Static smem 48KB.
// Same summation order as R11 -> bit-identical results.
// ---------------------------------------------------------------------------
#define TBM 256
#define TBN 128
#define TBK 32

__device__ __forceinline__ void gemm_load_regs(
    const float* __restrict__ A, const float* __restrict__ W,
    int m0, int n0, int k0, int K, int N, int tid,
    float4* areg, float4* breg)
{
#pragma unroll
    for (int i = 0; i < 8; i++) {
        int f   = tid + i * 256;
        int row = f >> 3;                 // 0..255
        int c4  = (f & 7) << 2;
        areg[i] = *(const float4*)&A[(size_t)(m0 + row) * K + k0 + c4];
    }
#pragma unroll
    for (int i = 0; i < 4; i++) {
        int f  = tid + i * 256;
        int r  = f >> 5;                  // 0..31
        int c4 = (f & 31) << 2;
        breg[i] = *(const float4*)&W[(size_t)(k0 + r) * N + n0 + c4];
    }
}

__device__ __forceinline__ void gemm_scatter(
    uint32_t* __restrict__ Asf, uint32_t* __restrict__ Bsf, int tid,
    const float4* areg, const float4* breg)
{
#pragma unroll
    for (int i = 0; i < 8; i++) {
        int f   = tid + i * 256;
        int row = f >> 3;
        int c4  = (f & 7) << 2;
        const float av[4] = {areg[i].x, areg[i].y, areg[i].z, areg[i].w};
        int mt = row >> 4;                // 0..15
        int g  = row & 15;
        int gl = (g & 7) << 2;
        int ib = (g >= 8) ? 1 : 0;
#pragma unroll
        for (int e = 0; e < 4; e++) {
            int col = c4 + e;
            int ks  = col >> 3;
            int c   = col & 7;
            int idx = ib | ((c >= 4) ? 2 : 0);
            int ln  = (gl | (c & 3)) ^ ks;
            Asf[(((mt << 2) + ks) << 7) + (ln << 2) + idx] = f2tf32(av[e]);
        }
    }
#pragma unroll
    for (int i = 0; i < 4; i++) {
        int f  = tid + i * 256;
        int r  = f >> 5;
        int c4 = (f & 31) << 2;
        const float bv[4] = {breg[i].x, breg[i].y, breg[i].z, breg[i].w};
        int ks = r >> 3;
        int kc = r & 7;
        int ib = (kc >= 4) ? 1 : 0;
        int kl = kc & 3;
#pragma unroll
        for (int e = 0; e < 4; e++) {
            int n  = c4 + e;
            int nt = n >> 3;              // 0..15
            int gn = n & 7;
            int ln = ((gn << 2) | kl) ^ (nt & 15);
            Bsf[(((nt << 2) + ks) << 6) + (ln << 1) + ib] = f2tf32(bv[e]);
        }
    }
}

__global__ __launch_bounds__(256, 1)
void gemm_tf32_b(int a_sel, float* a_ext,
                 const float* __restrict__ W,
                 const float* __restrict__ bias,
                 int c_sel, float* c_ext,
                 int M, int N, int K)
{
    const float* __restrict__ A = sel_buf(a_sel, a_ext);
    float* __restrict__ C = sel_buf(c_sel, c_ext);

    __shared__ uint32_t Asf[16 * 4 * 32 * 4];   // 32KB
    __shared__ uint32_t Bsf[16 * 4 * 32 * 2];   // 16KB

    const int tid  = threadIdx.x;
    const int lane = tid & 31;
    const int wid  = tid >> 5;
    const int wm   = wid >> 1;    // 0..3
    const int wn   = wid & 1;     // 0..1
    const int m0   = blockIdx.y * TBM;
    const int n0   = blockIdx.x * TBN;

    float acc[4][8][4];
#pragma unroll
    for (int i = 0; i < 4; i++)
#pragma unroll
        for (int j = 0; j < 8; j++)
#pragma unroll
            for (int r = 0; r < 4; r++) acc[i][j][r] = 0.f;

    float4 areg[8], breg[4];
    gemm_load_regs(A, W, m0, n0, 0, K, N, tid, areg, breg);

    const int nk = K / TBK;
    for (int kt = 0; kt < nk; kt++) {
        gemm_scatter(Asf, Bsf, tid, areg, breg);
        __syncthreads();   // frags ready

        if (kt + 1 < nk)
            gemm_load_regs(A, W, m0, n0, (kt + 1) * TBK, K, N, tid, areg, breg);

#pragma unroll
        for (int ks = 0; ks < 4; ks++) {
            uint32_t af[4][4];
            uint32_t bf[8][2];
#pragma unroll
            for (int am = 0; am < 4; am++) {
                int mt = (wm << 2) + am;
                *(uint4*)af[am] = *(const uint4*)&Asf[(((mt << 2) + ks) << 7) + ((lane ^ ks) << 2)];
            }
#pragma unroll
            for (int bn = 0; bn < 8; bn++) {
                int nt = (wn << 3) + bn;
                *(uint2*)bf[bn] = *(const uint2*)&Bsf[(((nt << 2) + ks) << 6) + ((lane ^ (nt & 15)) << 1)];
            }
#pragma unroll
            for (int am = 0; am < 4; am++)
#pragma unroll
                for (int bn = 0; bn < 8; bn++)
                    mma_tf32(acc[am][bn], af[am], bf[bn]);
        }
        __syncthreads();   // guard frag overwrite by next scatter
    }

    const int g = lane >> 2;
    const int t = lane & 3;
#pragma unroll
    for (int bn = 0; bn < 8; bn++) {
        int col = n0 + wn * 64 + bn * 8 + t * 2;
        float2 bb = *(const float2*)&bias[col];
#pragma unroll
        for (int am = 0; am < 4; am++) {
            int row = m0 + wm * 64 + am * 16 + g;
            float2 o0, o1;
            o0.x = acc[am][bn][0] + bb.x;  o0.y = acc[am][bn][1] + bb.y;
            o1.x = acc[am][bn][2] + bb.x;  o1.y = acc[am][bn][3] + bb.y;
            *(float2*)&C[(size_t)row * N + col]       = o0;
            *(float2*)&C[(size_t)(row + 8) * N + col] = o1;
        }
    }
}

// ---------------------------------------------------------------------------
// RoPE in place on g_q / g_k.
// ---------------------------------------------------------------------------
__global__ void rope_kernel(const float* __restrict__ cosb, const float* __restrict__ sinb)
{
    int idx = blockIdx.x * 256 + threadIdx.x;
    const int d  = idx & 63;  idx >>= 6;
    const int hh = idx % (NH_ + NKV_);
    const int bs = idx / (NH_ + NKV_);

    const float c1 = cosb[(size_t)bs * HD_ + d];
    const float s1 = sinb[(size_t)bs * HD_ + d];
    const float c2 = cosb[(size_t)bs * HD_ + d + 64];
    const float s2 = sinb[(size_t)bs * HD_ + d + 64];

    float* base;
    if (hh < NH_) base = g_q + ((size_t)bs * NH_ + hh) * HD_;
    else          base = g_k + ((size_t)bs * NKV_ + (hh - NH_)) * HD_;

    const float x1 = base[d];
    const float x2 = base[d + 64];
    base[d]      = x1 * c1 - x2 * s1;
    base[d + 64] = x2 * c2 + x1 * s2;
}

// ---------------------------------------------------------------------------
// bf16 tensor-core flash attention, fully error-compensated (R11, passing).
// ---------------------------------------------------------------------------
#define AQ2 128
#define AKT 32
#define QF_WORDS (8*8*32*4)
#define KF_WORDS (4*8*32*2)
#define VF_WORDS (16*2*32*2)

__device__ __forceinline__ void attn_load_regs(
    const float* __restrict__ Kg, const float* __restrict__ Vg,
    int b, int kvh, int j0, int tid,
    float4* kreg, float4* vreg0, float4* vreg1)
{
#pragma unroll
    for (int i = 0; i < 4; i++) {
        int f   = tid + i * 256;
        int key = f >> 5;
        int c4  = (f & 31) << 2;
        kreg[i] = *(const float4*)&Kg[(((size_t)b * S_ + j0 + key) * NKV_ + kvh) * HD_ + c4];
    }
#pragma unroll
    for (int i = 0; i < 2; i++) {
        int f   = tid + i * 256;
        int kp  = f >> 5;
        int c4  = (f & 31) << 2;
        vreg0[i] = *(const float4*)&Vg[(((size_t)b * S_ + j0 + 2*kp)     * NKV_ + kvh) * HD_ + c4];
        vreg1[i] = *(const float4*)&Vg[(((size_t)b * S_ + j0 + 2*kp + 1) * NKV_ + kvh) * HD_ + c4];
    }
}

__device__ __forceinline__ void attn_store_frags(
    uint32_t* __restrict__ KfHi, uint32_t* __restrict__ KfLo,
    uint32_t* __restrict__ VfHi, uint32_t* __restrict__ VfLo, int tid,
    const float4* kreg, const float4* vreg0, const float4* vreg1)
{
#pragma unroll
    for (int i = 0; i < 4; i++) {
        int f   = tid + i * 256;
        int key = f >> 5;
        int c4  = (f & 31) << 2;
        int nt  = key >> 3;
        int g   = key & 7;
        const float kv[4] = {kreg[i].x, kreg[i].y, kreg[i].z, kreg[i].w};
        int ks  = c4 >> 4;
        int base_uu = (c4 & 15) >> 1;
#pragma unroll
        for (int p = 0; p < 2; p++) {
            int c   = (c4 & 15) + 2 * p;
            int reg = (c >= 8) ? 1 : 0;
            int uu  = base_uu + p;
            int ln  = (g * 4 + (uu & 3)) ^ ks;
            int off = ((((nt << 3) + ks) << 5) + ln) * 2 + reg;
            uint32_t hi, lo;
            bf16_split2(kv[2*p], kv[2*p+1], hi, lo);
            KfHi[off] = hi;
            KfLo[off] = lo;
        }
    }
#pragma unroll
    for (int i = 0; i < 2; i++) {
        int f   = tid + i * 256;
        int kp  = f >> 5;
        int c4  = (f & 31) << 2;
        int kt  = kp >> 3;
        int uu  = kp & 3;
        int reg = ((kp & 7) >= 4) ? 1 : 0;
        const float v0[4] = {vreg0[i].x, vreg0[i].y, vreg0[i].z, vreg0[i].w};
        const float v1[4] = {vreg1[i].x, vreg1[i].y, vreg1[i].z, vreg1[i].w};
#pragma unroll
        for (int e = 0; e < 4; e++) {
            int hd  = c4 + e;
            int nt2 = hd >> 3;
            int g   = hd & 7;
            int ln  = (g * 4 + uu) ^ (nt2 & 7);
            int off = ((((nt2 << 1) + kt) << 5) + ln) * 2 + reg;
            uint32_t hi, lo;
            bf16_split2(v0[e], v1[e], hi, lo);
            VfHi[off] = hi;
            VfLo[off] = lo;
        }
    }
}

__global__ __launch_bounds__(256, 1)
void attn_mma_v2()
{
    extern __shared__ uint32_t smu[];
    uint32_t* QfHi = smu;
    uint32_t* QfLo = QfHi + QF_WORDS;
    uint32_t* KfHi = QfLo + QF_WORDS;
    uint32_t* KfLo = KfHi + KF_WORDS;
    uint32_t* VfHi = KfLo + KF_WORDS;
    uint32_t* VfLo = VfHi + VF_WORDS;

    const int tid  = threadIdx.x;
    const int lane = tid & 31;
    const int wid  = tid >> 5;
    const int u    = lane & 3;
    const int qd   = lane >> 2;
    const int bh   = blockIdx.y;
    const int b    = bh >> 4;
    const int h    = bh & 15;
    const int kvh  = h >> 2;
    const int q0   = blockIdx.x * AQ2;

    const float* __restrict__ Qg = g_q;
    const float* __restrict__ Kg = g_k;
    const float* __restrict__ Vg = g_v;

    {
        const int row  = tid >> 1;
        const int c0   = (tid & 1) * 64;
        const float* qrow = &Qg[(((size_t)b * S_ + q0 + row) * NH_ + h) * HD_];
        const int mt   = row >> 4;
        const int r15  = row & 15;
        const int g    = r15 & 7;
        const int rbit = (r15 >= 8) ? 1 : 0;
#pragma unroll
        for (int cc = 0; cc < 64; cc += 4) {
            float4 qv = *(const float4*)&qrow[c0 + cc];
            const float xv[4] = {qv.x * SCALE_, qv.y * SCALE_, qv.z * SCALE_, qv.w * SCALE_};
#pragma unroll
            for (int p = 0; p < 2; p++) {
                int col = c0 + cc + 2 * p;
                int ks  = col >> 4;
                int c   = col & 15;
                int reg = rbit + ((c >= 8) ? 2 : 0);
                int uu  = (c & 7) >> 1;
                int off = (((mt << 3) + ks) << 7) + ((g * 4 + uu) << 2) + reg;
                uint32_t hi, lo;
                bf16_split2(xv[2*p], xv[2*p+1], hi, lo);
                QfHi[off] = hi;
                QfLo[off] = lo;
            }
        }
    }

    float4 kreg[4], vreg0[2], vreg1[2];
    attn_load_regs(Kg, Vg, b, kvh, 0, tid, kreg, vreg0, vreg1);
    attn_store_frags(KfHi, KfLo, VfHi, VfLo, tid, kreg, vreg0, vreg1);

    float Oacc[16][4];
#pragma unroll
    for (int i = 0; i < 16; i++)
#pragma unroll
        for (int r = 0; r < 4; r++) Oacc[i][r] = 0.f;
    float m0 = -1.0e30f, m1 = -1.0e30f, l0 = 0.f, l1 = 0.f;

    __syncthreads();

    const int NTILES = S_ / AKT;

    for (int jt = 0; jt < NTILES; jt++) {
        if (jt + 1 < NTILES)
            attn_load_regs(Kg, Vg, b, kvh, (jt + 1) * AKT, tid, kreg, vreg0, vreg1);

        float Sacc[4][4];
#pragma unroll
        for (int i = 0; i < 4; i++)
#pragma unroll
            for (int r = 0; r < 4; r++) Sacc[i][r] = 0.f;

#pragma unroll
        for (int ks = 0; ks < 8; ks++) {
            uint32_t ahi[4], alo[4];
            int aoff = (((wid << 3) + ks) << 7) + (lane << 2);
            *(uint4*)ahi = *(const uint4*)&QfHi[aoff];
            *(uint4*)alo = *(const uint4*)&QfLo[aoff];
#pragma unroll
            for (int nt = 0; nt < 4; nt++) {
                int koff = ((((nt << 3) + ks) << 5) + (lane ^ ks)) * 2;
                uint32_t bh_[2], bl_[2];
                *(uint2*)bh_ = *(const uint2*)&KfHi[koff];
                *(uint2*)bl_ = *(const uint2*)&KfLo[koff];
                mma_bf16(Sacc[nt], ahi, bh_);
                mma_bf16(Sacc[nt], ahi, bl_);
                mma_bf16(Sacc[nt], alo, bh_);
            }
        }

        float mx0 = -1.0e30f, mx1 = -1.0e30f;
#pragma unroll
        for (int nt = 0; nt < 4; nt++) {
            mx0 = fmaxf(mx0, fmaxf(Sacc[nt][0], Sacc[nt][1]));
            mx1 = fmaxf(mx1, fmaxf(Sacc[nt][2], Sacc[nt][3]));
        }
        mx0 = fmaxf(mx0, __shfl_xor_sync(0xffffffffu, mx0, 1));
        mx0 = fmaxf(mx0, __shfl_xor_sync(0xffffffffu, mx0, 2));
        mx1 = fmaxf(mx1, __shfl_xor_sync(0xffffffffu, mx1, 1));
        mx1 = fmaxf(mx1, __shfl_xor_sync(0xffffffffu, mx1, 2));

        float mn0 = fmaxf(m0, mx0);
        float mn1 = fmaxf(m1, mx1);
        float fs0 = __expf(m0 - mn0);
        float fs1 = __expf(m1 - mn1);
        m0 = mn0;  m1 = mn1;

        float P[4][4];
        float s0 = 0.f, s1 = 0.f;
#pragma unroll
        for (int nt = 0; nt < 4; nt++) {
            P[nt][0] = __expf(Sacc[nt][0] - m0);
            P[nt][1] = __expf(Sacc[nt][1] - m0);
            P[nt][2] = __expf(Sacc[nt][2] - m1);
            P[nt][3] = __expf(Sacc[nt][3] - m1);
            s0 += P[nt][0] + P[nt][1];
            s1 += P[nt][2] + P[nt][3];
        }
        s0 += __shfl_xor_sync(0xffffffffu, s0, 1);
        s0 += __shfl_xor_sync(0xffffffffu, s0, 2);
        s1 += __shfl_xor_sync(0xffffffffu, s1, 1);
        s1 += __shfl_xor_sync(0xffffffffu, s1, 2);
        l0 = l0 * fs0 + s0;
        l1 = l1 * fs1 + s1;

#pragma unroll
        for (int i = 0; i < 16; i++) {
            Oacc[i][0] *= fs0;  Oacc[i][1] *= fs0;
            Oacc[i][2] *= fs1;  Oacc[i][3] *= fs1;
        }

#pragma unroll
        for (int kt = 0; kt < 2; kt++) {
            uint32_t ah[4], al[4];
            bf16_split2(P[2*kt][0],   P[2*kt][1],   ah[0], al[0]);
            bf16_split2(P[2*kt][2],   P[2*kt][3],   ah[1], al[1]);
            bf16_split2(P[2*kt+1][0], P[2*kt+1][1], ah[2], al[2]);
            bf16_split2(P[2*kt+1][2], P[2*kt+1][3], ah[3], al[3]);
#pragma unroll
            for (int nt2 = 0; nt2 < 16; nt2++) {
                int voff = ((((nt2 << 1) + kt) << 5) + (lane ^ (nt2 & 7))) * 2;
                uint32_t bvh[2], bvl[2];
                *(uint2*)bvh = *(const uint2*)&VfHi[voff];
                *(uint2*)bvl = *(const uint2*)&VfLo[voff];
                mma_bf16(Oacc[nt2], ah, bvh);
                mma_bf16(Oacc[nt2], ah, bvl);
                mma_bf16(Oacc[nt2], al, bvh);
            }
        }

        __syncthreads();
        if (jt + 1 < NTILES)
            attn_store_frags(KfHi, KfLo, VfHi, VfLo, tid, kreg, vreg0, vreg1);
        __syncthreads();
    }

    const float inv0 = 1.0f / l0;
    const float inv1 = 1.0f / l1;
    const int row0 = q0 + wid * 16 + qd;
    const size_t rbase0 = ((size_t)b * S_ + row0)     * (NH_ * HD_) + h * HD_ + 2 * u;
    const size_t rbase1 = ((size_t)b * S_ + row0 + 8) * (NH_ * HD_) + h * HD_ + 2 * u;
    float* __restrict__ Out = g_attn;
#pragma unroll
    for (int nt2 = 0; nt2 < 16; nt2++) {
        float2 o0, o1;
        o0.x = Oacc[nt2][0] * inv0;  o0.y = Oacc[nt2][1] * inv0;
        o1.x = Oacc[nt2][2] * inv1;  o1.y = Oacc[nt2][3] * inv1;
        *(float2*)&Out[rbase0 + nt2 * 8] = o0;
        *(float2*)&Out[rbase1 + nt2 * 8] = o1;
    }
}

// ---------------------------------------------------------------------------
extern "C" void kernel_launch(void* const* d_in, const int* in_sizes, int n_in,
                              void* d_out, int out_size)
{
    float* hidden = (float*)d_in[0];
    const float* cosb   = (const float*)d_in[1];
    const float* sinb   = (const float*)d_in[2];
    const float* Wq     = (const float*)d_in[3];
    const float* bq     = (const float*)d_in[4];
    const float* Wk     = (const float*)d_in[5];
    const float* bk     = (const float*)d_in[6];
    const float* Wv     = (const float*)d_in[7];
    const float* bv     = (const float*)d_in[8];
    const float* Wo     = (const float*)d_in[9];
    const float* bo     = (const float*)d_in[10];
    float* out = (float*)d_out;

    const int M = B_ * S_;   // 4096

    gemm_tf32_b<<<dim3((NH_*HD_) / TBN, M / TBM), 256>>>(BUF_EXT, hidden, Wq, bq, BUF_Q, nullptr, M, NH_*HD_, H_);
    gemm_tf32_b<<<dim3((NKV_*HD_) / TBN, M / TBM), 256>>>(BUF_EXT, hidden, Wk, bk, BUF_K, nullptr, M, NKV_*HD_, H_);
    gemm_tf32_b<<<dim3((NKV_*HD_) / TBN, M / TBM), 256>>>(BUF_EXT, hidden, Wv, bv, BUF_V, nullptr, M, NKV_*HD_, H_);

    {
        int total = B_ * S_ * (NH_ + NKV_) * 64;
        rope_kernel<<<total / 256, 256>>>(cosb, sinb);
    }

    {
        int smem = (2 * QF_WORDS + 2 * KF_WORDS + 2 * VF_WORDS) * (int)sizeof(uint32_t);  // 96KB
        cudaFuncSetAttribute(attn_mma_v2, cudaFuncAttributeMaxDynamicSharedMemorySize, smem);
        attn_mma_v2<<<dim3(S_ / AQ2, B_ * NH_), 256, smem>>>();
    }

    gemm_tf32_b<<<dim3(H_ / TBN, M / TBM), 256>>>(BUF_ATTN, nullptr, Wo, bo, BUF_EXT, out, M, H_, NH_*HD_);
}